// round 6
// baseline (speedup 1.0000x reference)
#include <cuda_runtime.h>
#include <cuda_bf16.h>
#include <cstdint>

// Problem constants (this instance): N=1e6 atoms, D=128, H=64, E=4, M=20000.
#define D_DIM 128
#define H_DIM 64
#define BM 128
#define KC 64             // K chunk (2 chunks of 64)
#define NTHREADS 256
#define E_MAX 8
#define PERM_CAP 1250000
#define HIST_BLOCKS 512

// SMEM: per-chunk tiles. A [128 rows][64 k] bf16 hi/lo, B [64 k][64 n] hi/lo.
#define OFF_AHI 0
#define OFF_ALO 16384
#define OFF_BHI 32768
#define OFF_BLO 40960
#define SMEM_TOTAL 49152

__device__ int g_count[E_MAX];
__device__ int g_cursor[E_MAX];
__device__ int g_done;
__device__ int g_perm[PERM_CAP];

// ---------------------------------------------------------------------------
// prep: zero output, counts, done flag; fill perm slots with -1
// ---------------------------------------------------------------------------
__global__ void k_prep(float* __restrict__ out, int M, int total_slots) {
    int i = blockIdx.x * blockDim.x + threadIdx.x;
    int stride = gridDim.x * blockDim.x;
    for (int j = i; j < M; j += stride) out[j] = 0.0f;
    for (int j = i; j < total_slots; j += stride) g_perm[j] = -1;
    if (i < E_MAX) g_count[i] = 0;
    if (i == E_MAX) g_done = 0;
}

// ---------------------------------------------------------------------------
// histogram + last-block exclusive scan (tile-padded)
// ---------------------------------------------------------------------------
__global__ void k_histscan(const int* __restrict__ zidx, int n, int E) {
    __shared__ int sh[E_MAX];
    if (threadIdx.x < E_MAX) sh[threadIdx.x] = 0;
    __syncthreads();
    int i = blockIdx.x * blockDim.x + threadIdx.x;
    int stride = gridDim.x * blockDim.x;
    for (int j = i; j < n; j += stride) atomicAdd(&sh[zidx[j]], 1);
    __syncthreads();
    if (threadIdx.x < E) atomicAdd(&g_count[threadIdx.x], sh[threadIdx.x]);
    __threadfence();
    __syncthreads();
    if (threadIdx.x == 0) {
        int t = atomicAdd(&g_done, 1);
        if (t == gridDim.x - 1) {   // last block performs the scan
            int off = 0;
            for (int e = 0; e < E; e++) {
                g_cursor[e] = off;
                off += ((g_count[e] + BM - 1) / BM) * BM;
            }
        }
    }
}

// ---------------------------------------------------------------------------
// scatter: block-aggregated counting-sort scatter of atom indices
// ---------------------------------------------------------------------------
__global__ void k_scatter(const int* __restrict__ zidx, int n) {
    __shared__ int s_cnt[E_MAX];
    __shared__ int s_off[E_MAX];
    if (threadIdx.x < E_MAX) s_cnt[threadIdx.x] = 0;
    __syncthreads();
    int i = blockIdx.x * blockDim.x + threadIdx.x;
    int e = -1;
    if (i < n) { e = zidx[i]; atomicAdd(&s_cnt[e], 1); }
    __syncthreads();
    if (threadIdx.x < E_MAX && s_cnt[threadIdx.x] > 0)
        s_off[threadIdx.x] = atomicAdd(&g_cursor[threadIdx.x], s_cnt[threadIdx.x]);
    __syncthreads();
    if (threadIdx.x < E_MAX) s_cnt[threadIdx.x] = 0;
    __syncthreads();
    if (i < n) {
        int pos = s_off[e] + atomicAdd(&s_cnt[e], 1);
        g_perm[pos] = i;
    }
}

__device__ __forceinline__ float sspf(float v) {
    return fmaxf(v, 0.0f) + log1pf(__expf(-fabsf(v))) - 0.69314718055994530942f;
}

__device__ __forceinline__ void mma_bf16(float* c, const uint32_t* a,
                                         const uint32_t b0, const uint32_t b1) {
    asm volatile(
        "mma.sync.aligned.m16n8k16.row.col.f32.bf16.bf16.f32 "
        "{%0,%1,%2,%3}, {%4,%5,%6,%7}, {%8,%9}, {%0,%1,%2,%3};"
        : "+f"(c[0]), "+f"(c[1]), "+f"(c[2]), "+f"(c[3])
        : "r"(a[0]), "r"(a[1]), "r"(a[2]), "r"(a[3]), "r"(b0), "r"(b1));
}
__device__ __forceinline__ void ldsm_x4(uint32_t* r, uint32_t addr) {
    asm volatile("ldmatrix.sync.aligned.m8n8.x4.shared.b16 {%0,%1,%2,%3}, [%4];"
                 : "=r"(r[0]), "=r"(r[1]), "=r"(r[2]), "=r"(r[3]) : "r"(addr));
}
__device__ __forceinline__ void ldsm_x4t(uint32_t* r, uint32_t addr) {
    asm volatile("ldmatrix.sync.aligned.m8n8.x4.trans.shared.b16 {%0,%1,%2,%3}, [%4];"
                 : "=r"(r[0]), "=r"(r[1]), "=r"(r[2]), "=r"(r[3]) : "r"(addr));
}
__device__ __forceinline__ uint32_t smem_u32(const void* p) {
    return (uint32_t)__cvta_generic_to_shared(p);
}

// ---------------------------------------------------------------------------
// main kernel: gathered 128x64x128 bf16 mma.sync GEMM (3-term hi/lo split),
// K chunked 2x64 for occ=2 so gather overlaps MMA across CTAs.
// ---------------------------------------------------------------------------
__global__ __launch_bounds__(NTHREADS, 2)
void k_main(const float* __restrict__ x, const int* __restrict__ zidx,
            const int* __restrict__ idx_m,
            const float* __restrict__ W1, const float* __restrict__ b1,
            const float* __restrict__ W2, const float* __restrict__ b2,
            float* __restrict__ out) {
    extern __shared__ char smem[];
    uint32_t* AhiW = reinterpret_cast<uint32_t*>(smem + OFF_AHI);
    uint32_t* AloW = reinterpret_cast<uint32_t*>(smem + OFF_ALO);
    uint32_t* BhiW = reinterpret_cast<uint32_t*>(smem + OFF_BHI);
    uint32_t* BloW = reinterpret_cast<uint32_t*>(smem + OFF_BLO);

    __shared__ int   s_orig[BM];
    __shared__ float b1s[H_DIM];
    __shared__ float w2s[H_DIM];
    __shared__ int   s_e;

    int tid = threadIdx.x;
    int wid = tid >> 5;
    int lane = tid & 31;
    int base_slot = blockIdx.x * BM;

    if (tid < BM) s_orig[tid] = g_perm[base_slot + tid];
    if (tid == 0) {
        int e = -1;
        for (int r = 0; r < BM; r++) {
            int o = g_perm[base_slot + r];
            if (o >= 0) { e = zidx[o]; break; }
        }
        s_e = e;
    }
    __syncthreads();
    int e = s_e;
    if (e < 0) return;

    const float* W1e = W1 + (size_t)e * D_DIM * H_DIM;
    if (tid < H_DIM) {
        b1s[tid] = b1[e * H_DIM + tid];
        w2s[tid] = W2[e * H_DIM + tid];
    }

    // fragment-lane decomposition
    int wm = wid & 3;
    int wn = wid >> 2;
    int g = lane >> 2;
    int tg = lane & 3;
    int lane7 = lane & 7;
    int sub = lane >> 3;
    int subm = sub & 1;
    int subh = sub >> 1;

    uint32_t aHiBase = smem_u32(AhiW), aLoBase = smem_u32(AloW);
    uint32_t bHiBase = smem_u32(BhiW), bLoBase = smem_u32(BloW);

    int aRowWord0 = (wm * 32 + 0 + subm * 8 + lane7) * 32;
    int aRowWord1 = (wm * 32 + 16 + subm * 8 + lane7) * 32;
    int aXor = 4 * lane7;
    int a4h = 4 * subh;
    int bConst0 = (subm * 8 + lane7) * 32 + ((4 * (wn * 4 + 0 + subh)) ^ (4 * lane7));
    int bConst1 = (subm * 8 + lane7) * 32 + ((4 * (wn * 4 + 2 + subh)) ^ (4 * lane7));

    // A-stage lane constants
    int aRowStage = wid * 2 + (lane >> 4);   // +16 per p
    int lane16 = lane & 15;
    int aC4 = lane16 >> 1, aHalf = lane16 & 1;

    float acc[2][4][4];
#pragma unroll
    for (int t = 0; t < 2; t++)
#pragma unroll
        for (int u = 0; u < 4; u++)
#pragma unroll
            for (int q = 0; q < 4; q++) acc[t][u][q] = 0.0f;

    for (int kc = 0; kc < 2; kc++) {
        const int kbase = kc * KC;
        // ---- stage A chunk: 128 rows x 64 k, hi/lo split, swizzled ----
#pragma unroll
        for (int p = 0; p < 8; p++) {
            int row = p * 16 + aRowStage;
            int o = s_orig[row];
            float4 v = make_float4(0.f, 0.f, 0.f, 0.f);
            if (o >= 0)
                v = *reinterpret_cast<const float4*>(
                    x + (size_t)o * D_DIM + kbase + lane16 * 4);
            __nv_bfloat16 hx = __float2bfloat16(v.x), hy = __float2bfloat16(v.y);
            __nv_bfloat16 hz = __float2bfloat16(v.z), hw = __float2bfloat16(v.w);
            float rx = v.x - __bfloat162float(hx), ry = v.y - __bfloat162float(hy);
            float rz = v.z - __bfloat162float(hz), rw = v.w - __bfloat162float(hw);
            __nv_bfloat162 hi01 = __halves2bfloat162(hx, hy);
            __nv_bfloat162 hi23 = __halves2bfloat162(hz, hw);
            __nv_bfloat162 lo01 = __floats2bfloat162_rn(rx, ry);
            __nv_bfloat162 lo23 = __floats2bfloat162_rn(rz, rw);
            uint2 hi2 = make_uint2(*reinterpret_cast<uint32_t*>(&hi01),
                                   *reinterpret_cast<uint32_t*>(&hi23));
            uint2 lo2 = make_uint2(*reinterpret_cast<uint32_t*>(&lo01),
                                   *reinterpret_cast<uint32_t*>(&lo23));
            int w = row * 32 + ((aC4 ^ (row & 7)) << 2) + aHalf * 2;
            *reinterpret_cast<uint2*>(&AhiW[w]) = hi2;
            *reinterpret_cast<uint2*>(&AloW[w]) = lo2;
        }
        // ---- stage B chunk: W1e rows [kbase, kbase+64), hi/lo, swizzled ----
#pragma unroll
        for (int i = 0; i < 4; i++) {
            int idx = i * NTHREADS + tid;     // 0..1023 float4s
            int k = idx >> 4;                 // 0..63
            int n4 = idx & 15;
            float4 wv = *reinterpret_cast<const float4*>(
                W1e + (size_t)(kbase + k) * H_DIM + n4 * 4);
            __nv_bfloat16 hx = __float2bfloat16(wv.x), hy = __float2bfloat16(wv.y);
            __nv_bfloat16 hz = __float2bfloat16(wv.z), hw = __float2bfloat16(wv.w);
            float rx = wv.x - __bfloat162float(hx), ry = wv.y - __bfloat162float(hy);
            float rz = wv.z - __bfloat162float(hz), rw = wv.w - __bfloat162float(hw);
            __nv_bfloat162 hi01 = __halves2bfloat162(hx, hy);
            __nv_bfloat162 hi23 = __halves2bfloat162(hz, hw);
            __nv_bfloat162 lo01 = __floats2bfloat162_rn(rx, ry);
            __nv_bfloat162 lo23 = __floats2bfloat162_rn(rz, rw);
            uint2 hi2 = make_uint2(*reinterpret_cast<uint32_t*>(&hi01),
                                   *reinterpret_cast<uint32_t*>(&hi23));
            uint2 lo2 = make_uint2(*reinterpret_cast<uint32_t*>(&lo01),
                                   *reinterpret_cast<uint32_t*>(&lo23));
            int c4 = n4 >> 1, half = n4 & 1;
            int w = k * 32 + ((c4 ^ (k & 7)) << 2) + half * 2;
            *reinterpret_cast<uint2*>(&BhiW[w]) = hi2;
            *reinterpret_cast<uint2*>(&BloW[w]) = lo2;
        }
        __syncthreads();

        // ---- 4 k16-steps in this chunk, 3 split terms ----
#pragma unroll
        for (int kb = 0; kb < 4; kb++) {
            int aOff = (8 * kb + a4h) ^ aXor;
            uint32_t ahi[2][4], alo[2][4], bhi[2][4], blo[2][4];
            ldsm_x4(ahi[0], aHiBase + (aRowWord0 + aOff) * 4);
            ldsm_x4(ahi[1], aHiBase + (aRowWord1 + aOff) * 4);
            ldsm_x4(alo[0], aLoBase + (aRowWord0 + aOff) * 4);
            ldsm_x4(alo[1], aLoBase + (aRowWord1 + aOff) * 4);
            ldsm_x4t(bhi[0], bHiBase + (kb * 512 + bConst0) * 4);
            ldsm_x4t(bhi[1], bHiBase + (kb * 512 + bConst1) * 4);
            ldsm_x4t(blo[0], bLoBase + (kb * 512 + bConst0) * 4);
            ldsm_x4t(blo[1], bLoBase + (kb * 512 + bConst1) * 4);
#pragma unroll
            for (int t = 0; t < 2; t++)
#pragma unroll
                for (int u = 0; u < 4; u++) {
                    int p = u >> 1, q = (u & 1) * 2;
                    mma_bf16(acc[t][u], ahi[t], bhi[p][q], bhi[p][q + 1]);
                    mma_bf16(acc[t][u], ahi[t], blo[p][q], blo[p][q + 1]);
                    mma_bf16(acc[t][u], alo[t], bhi[p][q], bhi[p][q + 1]);
                }
        }
        __syncthreads();   // buffers reused next chunk
    }

    // ---- epilogue: ssp + W2 dot per row; reduce across the 4 tg lanes ----
    float b2e = b2[e];
#pragma unroll
    for (int t = 0; t < 2; t++) {
        float p0 = 0.0f, p1 = 0.0f;
#pragma unroll
        for (int u = 0; u < 4; u++) {
            int c0 = wn * 32 + u * 8 + 2 * tg;
            p0 = fmaf(sspf(acc[t][u][0] + b1s[c0]),     w2s[c0],     p0);
            p0 = fmaf(sspf(acc[t][u][1] + b1s[c0 + 1]), w2s[c0 + 1], p0);
            p1 = fmaf(sspf(acc[t][u][2] + b1s[c0]),     w2s[c0],     p1);
            p1 = fmaf(sspf(acc[t][u][3] + b1s[c0 + 1]), w2s[c0 + 1], p1);
        }
        p0 += __shfl_xor_sync(0xffffffffu, p0, 1);
        p0 += __shfl_xor_sync(0xffffffffu, p0, 2);
        p1 += __shfl_xor_sync(0xffffffffu, p1, 1);
        p1 += __shfl_xor_sync(0xffffffffu, p1, 2);
        if (tg == 0) {
            int r0 = wm * 32 + t * 16 + g;
            int o0 = s_orig[r0];
            int o1 = s_orig[r0 + 8];
            float bias = (wn == 0) ? b2e : 0.0f;
            if (o0 >= 0) atomicAdd(&out[idx_m[o0]], p0 + bias);
            if (o1 >= 0) atomicAdd(&out[idx_m[o1]], p1 + bias);
        }
    }
}

// ---------------------------------------------------------------------------
extern "C" void kernel_launch(void* const* d_in, const int* in_sizes, int n_in,
                              void* d_out, int out_size) {
    const float* x    = (const float*)d_in[0];
    const int*   zidx = (const int*)d_in[1];
    const int*   idxm = (const int*)d_in[2];
    const float* W1   = (const float*)d_in[3];
    const float* b1   = (const float*)d_in[4];
    const float* W2   = (const float*)d_in[5];
    const float* b2   = (const float*)d_in[6];
    float* out = (float*)d_out;

    int N = in_sizes[1];
    int E = in_sizes[6];
    int M = out_size;

    int ntiles = (N + BM - 1) / BM + E;
    int total_slots = ntiles * BM;
    if (total_slots > PERM_CAP) total_slots = PERM_CAP;

    static int smem_set = 0;
    if (!smem_set) {
        cudaFuncSetAttribute(k_main, cudaFuncAttributeMaxDynamicSharedMemorySize,
                             SMEM_TOTAL);
        smem_set = 1;
    }

    // 4 launches; with the 2 harness launches ahead, k_main is overall #6
    // (where ncu -s 5 -c 1 lands).
    k_prep<<<256, 256>>>(out, M, total_slots);
    k_histscan<<<HIST_BLOCKS, 256>>>(zidx, N, E);
    k_scatter<<<(N + 255) / 256, 256>>>(zidx, N);
    k_main<<<ntiles, NTHREADS, SMEM_TOTAL>>>(x, zidx, idxm, W1, b1, W2, b2, out);
}

// round 7
// speedup vs baseline: 1.1182x; 1.1182x over previous
#include <cuda_runtime.h>
#include <cuda_bf16.h>
#include <cstdint>

// Problem constants (this instance): N=1e6 atoms, D=128, H=64, E=4, M=20000.
#define D_DIM 128
#define H_DIM 64
#define BM 128
#define NTHREADS 256
#define E_MAX 8
#define PERM_CAP 1250000
#define HIST_BLOCKS 512

// SMEM layout (dynamic, bytes): A [128 rows][128 k] bf16 hi/lo (32KB each),
// B [128 k][64 n] bf16 hi/lo (16KB each). Total 96KB -> occ 2.
#define OFF_AHI 0
#define OFF_ALO 32768
#define OFF_BHI 65536
#define OFF_BLO 81920
#define SMEM_TOTAL 98304

// B tile global image: per element, 4096 u32 words (16KB), exact smem layout.
#define BWORDS 4096

__device__ int g_count[E_MAX];
__device__ int g_cursor[E_MAX];
__device__ int g_done;
__device__ int g_perm[PERM_CAP];
__device__ uint32_t g_Whi[E_MAX * BWORDS];
__device__ uint32_t g_Wlo[E_MAX * BWORDS];

// ---------------------------------------------------------------------------
// prep: zero output/counters, fill perm with -1, AND pre-convert W1 into the
// swizzled bf16 hi/lo tile image (done once; k_main then just copies bytes).
// ---------------------------------------------------------------------------
__global__ void k_prep(float* __restrict__ out, const float* __restrict__ W1,
                       int E, int M, int total_slots) {
    int i = blockIdx.x * blockDim.x + threadIdx.x;
    int stride = gridDim.x * blockDim.x;
    for (int j = i; j < M; j += stride) out[j] = 0.0f;
    for (int j = i; j < total_slots; j += stride) g_perm[j] = -1;
    if (i < E_MAX) g_count[i] = 0;
    if (i == E_MAX) g_done = 0;

    int nitems = E * D_DIM * (H_DIM / 8);          // float4 pairs? -> per n4 of 4
    // item: e, k (0..127), n4 (0..15) -> one float4 of W1
    for (int it = i; it < E * D_DIM * 16; it += stride) {
        int e = it >> 11;
        int k = (it >> 4) & 127;
        int n4 = it & 15;
        float4 v = *reinterpret_cast<const float4*>(
            W1 + (size_t)e * D_DIM * H_DIM + (size_t)k * H_DIM + n4 * 4);
        __nv_bfloat16 hx = __float2bfloat16(v.x), hy = __float2bfloat16(v.y);
        __nv_bfloat16 hz = __float2bfloat16(v.z), hw = __float2bfloat16(v.w);
        float rx = v.x - __bfloat162float(hx), ry = v.y - __bfloat162float(hy);
        float rz = v.z - __bfloat162float(hz), rw = v.w - __bfloat162float(hw);
        __nv_bfloat162 hi01 = __halves2bfloat162(hx, hy);
        __nv_bfloat162 hi23 = __halves2bfloat162(hz, hw);
        __nv_bfloat162 lo01 = __floats2bfloat162_rn(rx, ry);
        __nv_bfloat162 lo23 = __floats2bfloat162_rn(rz, rw);
        int w = e * BWORDS + k * 32 + (((n4 >> 1) ^ (k & 7)) << 2) + (n4 & 1) * 2;
        g_Whi[w]     = *reinterpret_cast<uint32_t*>(&hi01);
        g_Whi[w + 1] = *reinterpret_cast<uint32_t*>(&hi23);
        g_Wlo[w]     = *reinterpret_cast<uint32_t*>(&lo01);
        g_Wlo[w + 1] = *reinterpret_cast<uint32_t*>(&lo23);
    }
    (void)nitems;
}

// ---------------------------------------------------------------------------
__global__ void k_histscan(const int* __restrict__ zidx, int n, int E) {
    __shared__ int sh[E_MAX];
    if (threadIdx.x < E_MAX) sh[threadIdx.x] = 0;
    __syncthreads();
    int i = blockIdx.x * blockDim.x + threadIdx.x;
    int stride = gridDim.x * blockDim.x;
    for (int j = i; j < n; j += stride) atomicAdd(&sh[zidx[j]], 1);
    __syncthreads();
    if (threadIdx.x < E) atomicAdd(&g_count[threadIdx.x], sh[threadIdx.x]);
    __threadfence();
    __syncthreads();
    if (threadIdx.x == 0) {
        int t = atomicAdd(&g_done, 1);
        if (t == gridDim.x - 1) {
            int off = 0;
            for (int e = 0; e < E; e++) {
                g_cursor[e] = off;
                off += ((g_count[e] + BM - 1) / BM) * BM;
            }
        }
    }
}

__global__ void k_scatter(const int* __restrict__ zidx, int n) {
    __shared__ int s_cnt[E_MAX];
    __shared__ int s_off[E_MAX];
    if (threadIdx.x < E_MAX) s_cnt[threadIdx.x] = 0;
    __syncthreads();
    int i = blockIdx.x * blockDim.x + threadIdx.x;
    int e = -1;
    if (i < n) { e = zidx[i]; atomicAdd(&s_cnt[e], 1); }
    __syncthreads();
    if (threadIdx.x < E_MAX && s_cnt[threadIdx.x] > 0)
        s_off[threadIdx.x] = atomicAdd(&g_cursor[threadIdx.x], s_cnt[threadIdx.x]);
    __syncthreads();
    if (threadIdx.x < E_MAX) s_cnt[threadIdx.x] = 0;
    __syncthreads();
    if (i < n) {
        int pos = s_off[e] + atomicAdd(&s_cnt[e], 1);
        g_perm[pos] = i;
    }
}

__device__ __forceinline__ float sspf(float v) {
    return fmaxf(v, 0.0f) + log1pf(__expf(-fabsf(v))) - 0.69314718055994530942f;
}

__device__ __forceinline__ void mma_bf16(float* c, const uint32_t* a,
                                         const uint32_t b0, const uint32_t b1) {
    asm volatile(
        "mma.sync.aligned.m16n8k16.row.col.f32.bf16.bf16.f32 "
        "{%0,%1,%2,%3}, {%4,%5,%6,%7}, {%8,%9}, {%0,%1,%2,%3};"
        : "+f"(c[0]), "+f"(c[1]), "+f"(c[2]), "+f"(c[3])
        : "r"(a[0]), "r"(a[1]), "r"(a[2]), "r"(a[3]), "r"(b0), "r"(b1));
}
__device__ __forceinline__ void ldsm_x4(uint32_t* r, uint32_t addr) {
    asm volatile("ldmatrix.sync.aligned.m8n8.x4.shared.b16 {%0,%1,%2,%3}, [%4];"
                 : "=r"(r[0]), "=r"(r[1]), "=r"(r[2]), "=r"(r[3]) : "r"(addr));
}
__device__ __forceinline__ void ldsm_x4t(uint32_t* r, uint32_t addr) {
    asm volatile("ldmatrix.sync.aligned.m8n8.x4.trans.shared.b16 {%0,%1,%2,%3}, [%4];"
                 : "=r"(r[0]), "=r"(r[1]), "=r"(r[2]), "=r"(r[3]) : "r"(addr));
}
__device__ __forceinline__ uint32_t smem_u32(const void* p) {
    return (uint32_t)__cvta_generic_to_shared(p);
}
__device__ __forceinline__ uint32_t cvt_bf16x2(float v1, float v0) {
    uint32_t r;   // r.lo = bf16(v0), r.hi = bf16(v1)
    asm("cvt.rn.bf16x2.f32 %0, %1, %2;" : "=r"(r) : "f"(v1), "f"(v0));
    return r;
}

// ---------------------------------------------------------------------------
// main kernel: gathered 128x64x128 bf16 mma.sync GEMM (3-term hi/lo split),
// single staging phase + single barrier; W1 tiles pre-converted in k_prep.
// ---------------------------------------------------------------------------
__global__ __launch_bounds__(NTHREADS, 2)
void k_main(const float* __restrict__ x, const int* __restrict__ zidx,
            const int* __restrict__ idx_m,
            const float* __restrict__ W1, const float* __restrict__ b1,
            const float* __restrict__ W2, const float* __restrict__ b2,
            float* __restrict__ out) {
    extern __shared__ char smem[];
    uint32_t* AhiW = reinterpret_cast<uint32_t*>(smem + OFF_AHI);
    uint32_t* AloW = reinterpret_cast<uint32_t*>(smem + OFF_ALO);
    uint32_t* BhiW = reinterpret_cast<uint32_t*>(smem + OFF_BHI);
    uint32_t* BloW = reinterpret_cast<uint32_t*>(smem + OFF_BLO);

    __shared__ int   s_orig[BM];
    __shared__ float b1s[H_DIM];
    __shared__ float w2s[H_DIM];
    __shared__ int   s_e;

    int tid = threadIdx.x;
    int wid = tid >> 5;
    int lane = tid & 31;
    int base_slot = blockIdx.x * BM;

    if (tid < BM) s_orig[tid] = g_perm[base_slot + tid];
    if (tid == 0) {
        int e = -1;
        for (int r = 0; r < BM; r++) {
            int o = g_perm[base_slot + r];
            if (o >= 0) { e = zidx[o]; break; }
        }
        s_e = e;
    }
    __syncthreads();
    int e = s_e;
    if (e < 0) return;

    if (tid < H_DIM) {
        b1s[tid] = b1[e * H_DIM + tid];
        w2s[tid] = W2[e * H_DIM + tid];
    }

    // ---- stage A: warp-per-row coalesced gather, PRMT hi / packed-cvt lo ----
    // word = row*64 + ((f4>>1) ^ (row&7))*4 + (f4&1)*2, f4 = lane (0..31)
    {
        int f4 = lane;
        int woff_base = ((f4 >> 1) << 2) + (f4 & 1) * 2;   // pre-xor part
#pragma unroll
        for (int p = 0; p < 16; p++) {
            int row = p * 8 + wid;
            int o = s_orig[row];
            float4 v = make_float4(0.f, 0.f, 0.f, 0.f);
            if (o >= 0)
                v = *reinterpret_cast<const float4*>(x + (size_t)o * D_DIM + f4 * 4);
            uint32_t xi0 = __float_as_uint(v.x), xi1 = __float_as_uint(v.y);
            uint32_t xi2 = __float_as_uint(v.z), xi3 = __float_as_uint(v.w);
            uint32_t h01 = __byte_perm(xi0, xi1, 0x7632);
            uint32_t h23 = __byte_perm(xi2, xi3, 0x7632);
            float l0 = v.x - __uint_as_float(xi0 & 0xffff0000u);
            float l1 = v.y - __uint_as_float(xi1 & 0xffff0000u);
            float l2 = v.z - __uint_as_float(xi2 & 0xffff0000u);
            float l3 = v.w - __uint_as_float(xi3 & 0xffff0000u);
            uint32_t l01 = cvt_bf16x2(l1, l0);
            uint32_t l23 = cvt_bf16x2(l3, l2);
            int w = row * 64 + ((((f4 >> 1) ^ (row & 7)) << 2) + (f4 & 1) * 2);
            *reinterpret_cast<uint2*>(&AhiW[w]) = make_uint2(h01, h23);
            *reinterpret_cast<uint2*>(&AloW[w]) = make_uint2(l01, l23);
        }
        (void)woff_base;
    }
    // ---- stage B: raw copy of pre-converted, pre-swizzled W1 tile image ----
    {
        const uint4* ghi = reinterpret_cast<const uint4*>(&g_Whi[e * BWORDS]);
        const uint4* glo = reinterpret_cast<const uint4*>(&g_Wlo[e * BWORDS]);
        uint4* shi = reinterpret_cast<uint4*>(BhiW);
        uint4* slo = reinterpret_cast<uint4*>(BloW);
#pragma unroll
        for (int i = 0; i < 4; i++) {
            int idx = i * NTHREADS + tid;   // 0..1023 uint4
            shi[idx] = ghi[idx];
            slo[idx] = glo[idx];
        }
    }
    __syncthreads();

    // ---- mainloop: warp tile 32(m) x 32(n), 8 k16-steps, 3 split terms ----
    int wm = wid & 3;
    int wn = wid >> 2;
    int g = lane >> 2;
    int tg = lane & 3;
    int lane7 = lane & 7;
    int sub = lane >> 3;
    int subm = sub & 1;
    int subh = sub >> 1;

    uint32_t aHiBase = smem_u32(AhiW), aLoBase = smem_u32(AloW);
    uint32_t bHiBase = smem_u32(BhiW), bLoBase = smem_u32(BloW);

    int aRowWord0 = (wm * 32 + 0 + subm * 8 + lane7) * 64;
    int aRowWord1 = (wm * 32 + 16 + subm * 8 + lane7) * 64;
    int aXor = 4 * lane7;
    int a4h = 4 * subh;
    int bConst0 = (subm * 8 + lane7) * 32 + ((4 * (wn * 4 + 0 + subh)) ^ (4 * lane7));
    int bConst1 = (subm * 8 + lane7) * 32 + ((4 * (wn * 4 + 2 + subh)) ^ (4 * lane7));

    float acc[2][4][4];
#pragma unroll
    for (int t = 0; t < 2; t++)
#pragma unroll
        for (int u = 0; u < 4; u++)
#pragma unroll
            for (int q = 0; q < 4; q++) acc[t][u][q] = 0.0f;

#pragma unroll
    for (int kb = 0; kb < 8; kb++) {
        int aOff = (8 * kb + a4h) ^ aXor;
        uint32_t ahi[2][4], alo[2][4], bhi[2][4], blo[2][4];
        ldsm_x4(ahi[0], aHiBase + (aRowWord0 + aOff) * 4);
        ldsm_x4(ahi[1], aHiBase + (aRowWord1 + aOff) * 4);
        ldsm_x4(alo[0], aLoBase + (aRowWord0 + aOff) * 4);
        ldsm_x4(alo[1], aLoBase + (aRowWord1 + aOff) * 4);
        ldsm_x4t(bhi[0], bHiBase + (kb * 512 + bConst0) * 4);
        ldsm_x4t(bhi[1], bHiBase + (kb * 512 + bConst1) * 4);
        ldsm_x4t(blo[0], bLoBase + (kb * 512 + bConst0) * 4);
        ldsm_x4t(blo[1], bLoBase + (kb * 512 + bConst1) * 4);
#pragma unroll
        for (int t = 0; t < 2; t++)
#pragma unroll
            for (int u = 0; u < 4; u++) {
                int p = u >> 1, q = (u & 1) * 2;
                mma_bf16(acc[t][u], ahi[t], bhi[p][q], bhi[p][q + 1]);
                mma_bf16(acc[t][u], ahi[t], blo[p][q], blo[p][q + 1]);
                mma_bf16(acc[t][u], alo[t], bhi[p][q], bhi[p][q + 1]);
            }
    }

    // ---- epilogue: ssp + W2 dot per row; reduce across the 4 tg lanes ----
    float b2e = b2[e];
#pragma unroll
    for (int t = 0; t < 2; t++) {
        float p0 = 0.0f, p1 = 0.0f;
#pragma unroll
        for (int u = 0; u < 4; u++) {
            int c0 = wn * 32 + u * 8 + 2 * tg;
            p0 = fmaf(sspf(acc[t][u][0] + b1s[c0]),     w2s[c0],     p0);
            p0 = fmaf(sspf(acc[t][u][1] + b1s[c0 + 1]), w2s[c0 + 1], p0);
            p1 = fmaf(sspf(acc[t][u][2] + b1s[c0]),     w2s[c0],     p1);
            p1 = fmaf(sspf(acc[t][u][3] + b1s[c0 + 1]), w2s[c0 + 1], p1);
        }
        p0 += __shfl_xor_sync(0xffffffffu, p0, 1);
        p0 += __shfl_xor_sync(0xffffffffu, p0, 2);
        p1 += __shfl_xor_sync(0xffffffffu, p1, 1);
        p1 += __shfl_xor_sync(0xffffffffu, p1, 2);
        if (tg == 0) {
            int r0 = wm * 32 + t * 16 + g;
            int o0 = s_orig[r0];
            int o1 = s_orig[r0 + 8];
            float bias = (wn == 0) ? b2e : 0.0f;
            if (o0 >= 0) atomicAdd(&out[idx_m[o0]], p0 + bias);
            if (o1 >= 0) atomicAdd(&out[idx_m[o1]], p1 + bias);
        }
    }
}

// ---------------------------------------------------------------------------
extern "C" void kernel_launch(void* const* d_in, const int* in_sizes, int n_in,
                              void* d_out, int out_size) {
    const float* x    = (const float*)d_in[0];
    const int*   zidx = (const int*)d_in[1];
    const int*   idxm = (const int*)d_in[2];
    const float* W1   = (const float*)d_in[3];
    const float* b1   = (const float*)d_in[4];
    const float* W2   = (const float*)d_in[5];
    const float* b2   = (const float*)d_in[6];
    float* out = (float*)d_out;

    int N = in_sizes[1];
    int E = in_sizes[6];
    int M = out_size;

    int ntiles = (N + BM - 1) / BM + E;
    int total_slots = ntiles * BM;
    if (total_slots > PERM_CAP) total_slots = PERM_CAP;

    static int smem_set = 0;
    if (!smem_set) {
        cudaFuncSetAttribute(k_main, cudaFuncAttributeMaxDynamicSharedMemorySize,
                             SMEM_TOTAL);
        smem_set = 1;
    }

    // 4 launches -> k_main is overall launch #6 (ncu -s 5 -c 1 target).
    k_prep<<<256, 256>>>(out, W1, E, M, total_slots);
    k_histscan<<<HIST_BLOCKS, 256>>>(zidx, N, E);
    k_scatter<<<(N + 255) / 256, 256>>>(zidx, N);
    k_main<<<ntiles, NTHREADS, SMEM_TOTAL>>>(x, zidx, idxm, W1, b1, W2, b2, out);
}

// round 8
// speedup vs baseline: 1.5857x; 1.4180x over previous
#include <cuda_runtime.h>
#include <cuda_bf16.h>
#include <cstdint>

// Problem constants (this instance): N=1e6 atoms, D=128, H=64, E=4, M=20000.
#define D_DIM 128
#define H_DIM 64
#define BM 128
#define NT 512
#define E_MAX 8
#define PERM_CAP 1250000
#define HIST_BLOCKS 512
#define GRID_PERSIST 148

// dynamic SMEM layout (bytes)
#define OFF_AHI 0
#define OFF_ALO 32768
#define OFF_BHI 65536
#define OFF_BLO 81920
#define OFF_SORIG 98304      // 2 x 128 ints
#define OFF_B1ALL 99328      // E_MAX*64 floats
#define OFF_W2ALL 101376     // E_MAX*64 floats
#define SMEM_TOTAL 103936

#define BWORDS 4096          // per-element W1 image: 4096 u32 (16KB)

__device__ int g_count[E_MAX];
__device__ int g_cursor[E_MAX];
__device__ int g_done;
__device__ int g_perm[PERM_CAP];
__device__ uint32_t g_Whi[E_MAX * BWORDS];
__device__ uint32_t g_Wlo[E_MAX * BWORDS];

// ---------------------------------------------------------------------------
// prep: zero output/counters, fill perm with -1, pre-convert W1 into the
// swizzled bf16 hi/lo tile image (once).
// ---------------------------------------------------------------------------
__global__ void k_prep(float* __restrict__ out, const float* __restrict__ W1,
                       int E, int M, int total_slots) {
    int i = blockIdx.x * blockDim.x + threadIdx.x;
    int stride = gridDim.x * blockDim.x;
    for (int j = i; j < M; j += stride) out[j] = 0.0f;
    for (int j = i; j < total_slots; j += stride) g_perm[j] = -1;
    if (i < E_MAX) g_count[i] = 0;
    if (i == E_MAX) g_done = 0;

    for (int it = i; it < E * D_DIM * 16; it += stride) {
        int e = it >> 11;
        int k = (it >> 4) & 127;
        int n4 = it & 15;
        float4 v = *reinterpret_cast<const float4*>(
            W1 + (size_t)e * D_DIM * H_DIM + (size_t)k * H_DIM + n4 * 4);
        __nv_bfloat16 hx = __float2bfloat16(v.x), hy = __float2bfloat16(v.y);
        __nv_bfloat16 hz = __float2bfloat16(v.z), hw = __float2bfloat16(v.w);
        float rx = v.x - __bfloat162float(hx), ry = v.y - __bfloat162float(hy);
        float rz = v.z - __bfloat162float(hz), rw = v.w - __bfloat162float(hw);
        __nv_bfloat162 hi01 = __halves2bfloat162(hx, hy);
        __nv_bfloat162 hi23 = __halves2bfloat162(hz, hw);
        __nv_bfloat162 lo01 = __floats2bfloat162_rn(rx, ry);
        __nv_bfloat162 lo23 = __floats2bfloat162_rn(rz, rw);
        int w = e * BWORDS + k * 32 + (((n4 >> 1) ^ (k & 7)) << 2) + (n4 & 1) * 2;
        g_Whi[w]     = *reinterpret_cast<uint32_t*>(&hi01);
        g_Whi[w + 1] = *reinterpret_cast<uint32_t*>(&hi23);
        g_Wlo[w]     = *reinterpret_cast<uint32_t*>(&lo01);
        g_Wlo[w + 1] = *reinterpret_cast<uint32_t*>(&lo23);
    }
}

// ---------------------------------------------------------------------------
__global__ void k_histscan(const int* __restrict__ zidx, int n, int E) {
    __shared__ int sh[E_MAX];
    if (threadIdx.x < E_MAX) sh[threadIdx.x] = 0;
    __syncthreads();
    int i = blockIdx.x * blockDim.x + threadIdx.x;
    int stride = gridDim.x * blockDim.x;
    for (int j = i; j < n; j += stride) atomicAdd(&sh[zidx[j]], 1);
    __syncthreads();
    if (threadIdx.x < E) atomicAdd(&g_count[threadIdx.x], sh[threadIdx.x]);
    __threadfence();
    __syncthreads();
    if (threadIdx.x == 0) {
        int t = atomicAdd(&g_done, 1);
        if (t == gridDim.x - 1) {
            int off = 0;
            for (int e = 0; e < E; e++) {
                g_cursor[e] = off;
                off += ((g_count[e] + BM - 1) / BM) * BM;
            }
        }
    }
}

__global__ void k_scatter(const int* __restrict__ zidx, int n) {
    __shared__ int s_cnt[E_MAX];
    __shared__ int s_off[E_MAX];
    if (threadIdx.x < E_MAX) s_cnt[threadIdx.x] = 0;
    __syncthreads();
    int i = blockIdx.x * blockDim.x + threadIdx.x;
    int e = -1;
    if (i < n) { e = zidx[i]; atomicAdd(&s_cnt[e], 1); }
    __syncthreads();
    if (threadIdx.x < E_MAX && s_cnt[threadIdx.x] > 0)
        s_off[threadIdx.x] = atomicAdd(&g_cursor[threadIdx.x], s_cnt[threadIdx.x]);
    __syncthreads();
    if (threadIdx.x < E_MAX) s_cnt[threadIdx.x] = 0;
    __syncthreads();
    if (i < n) {
        int pos = s_off[e] + atomicAdd(&s_cnt[e], 1);
        g_perm[pos] = i;
    }
}

// fast shifted softplus: log(0.5 + 0.5*e^v); inputs here are O(10) so no
// overflow concerns.
__device__ __forceinline__ float sspf(float v) {
    return __logf(fmaf(0.5f, __expf(v), 0.5f));
}

__device__ __forceinline__ void mma_bf16(float* c, const uint32_t* a,
                                         const uint32_t b0, const uint32_t b1) {
    asm volatile(
        "mma.sync.aligned.m16n8k16.row.col.f32.bf16.bf16.f32 "
        "{%0,%1,%2,%3}, {%4,%5,%6,%7}, {%8,%9}, {%0,%1,%2,%3};"
        : "+f"(c[0]), "+f"(c[1]), "+f"(c[2]), "+f"(c[3])
        : "r"(a[0]), "r"(a[1]), "r"(a[2]), "r"(a[3]), "r"(b0), "r"(b1));
}
__device__ __forceinline__ void ldsm_x4(uint32_t* r, uint32_t addr) {
    asm volatile("ldmatrix.sync.aligned.m8n8.x4.shared.b16 {%0,%1,%2,%3}, [%4];"
                 : "=r"(r[0]), "=r"(r[1]), "=r"(r[2]), "=r"(r[3]) : "r"(addr));
}
__device__ __forceinline__ void ldsm_x4t(uint32_t* r, uint32_t addr) {
    asm volatile("ldmatrix.sync.aligned.m8n8.x4.trans.shared.b16 {%0,%1,%2,%3}, [%4];"
                 : "=r"(r[0]), "=r"(r[1]), "=r"(r[2]), "=r"(r[3]) : "r"(addr));
}
__device__ __forceinline__ uint32_t smem_u32(const void* p) {
    return (uint32_t)__cvta_generic_to_shared(p);
}
__device__ __forceinline__ uint32_t cvt_bf16x2(float v1, float v0) {
    uint32_t r;
    asm("cvt.rn.bf16x2.f32 %0, %1, %2;" : "=r"(r) : "f"(v1), "f"(v0));
    return r;
}

// convert one float4 (4 k-values of one row) to hi/lo bf16 and store swizzled
__device__ __forceinline__ void store_a(uint32_t* AhiW, uint32_t* AloW,
                                        float4 v, int row, int lane) {
    uint32_t xi0 = __float_as_uint(v.x), xi1 = __float_as_uint(v.y);
    uint32_t xi2 = __float_as_uint(v.z), xi3 = __float_as_uint(v.w);
    uint32_t h01 = __byte_perm(xi0, xi1, 0x7632);
    uint32_t h23 = __byte_perm(xi2, xi3, 0x7632);
    float l0 = v.x - __uint_as_float(xi0 & 0xffff0000u);
    float l1 = v.y - __uint_as_float(xi1 & 0xffff0000u);
    float l2 = v.z - __uint_as_float(xi2 & 0xffff0000u);
    float l3 = v.w - __uint_as_float(xi3 & 0xffff0000u);
    uint32_t l01 = cvt_bf16x2(l1, l0);
    uint32_t l23 = cvt_bf16x2(l3, l2);
    int w = row * 64 + ((((lane >> 1) ^ (row & 7)) << 2) + (lane & 1) * 2);
    *reinterpret_cast<uint2*>(&AhiW[w]) = make_uint2(h01, h23);
    *reinterpret_cast<uint2*>(&AloW[w]) = make_uint2(l01, l23);
}

// ---------------------------------------------------------------------------
// persistent main kernel: each CTA owns a contiguous tile range; tile t+1's
// gather is prefetched into registers during tile t's MMA+epilogue; W1 image
// re-staged only on element change.
// ---------------------------------------------------------------------------
__global__ __launch_bounds__(NT, 1)
void k_main(const float* __restrict__ x, const int* __restrict__ zidx,
            const int* __restrict__ idx_m,
            const float* __restrict__ W1, const float* __restrict__ b1,
            const float* __restrict__ W2, const float* __restrict__ b2,
            float* __restrict__ out, int ntiles) {
    extern __shared__ char smem[];
    uint32_t* AhiW = reinterpret_cast<uint32_t*>(smem + OFF_AHI);
    uint32_t* AloW = reinterpret_cast<uint32_t*>(smem + OFF_ALO);
    uint32_t* BhiW = reinterpret_cast<uint32_t*>(smem + OFF_BHI);
    uint32_t* BloW = reinterpret_cast<uint32_t*>(smem + OFF_BLO);
    int*   sOrig = reinterpret_cast<int*>(smem + OFF_SORIG);   // [2][128]
    float* b1all = reinterpret_cast<float*>(smem + OFF_B1ALL);
    float* w2all = reinterpret_cast<float*>(smem + OFF_W2ALL);

    int tid = threadIdx.x;
    int wid = tid >> 5;
    int lane = tid & 31;

    int q = (ntiles + gridDim.x - 1) / gridDim.x;
    int tstart = blockIdx.x * q;
    int tend = min(ntiles, tstart + q);
    if (tstart >= tend) return;

    // preload all elements' b1 / W2 (E*64 <= 512)
    if (tid < E_MAX * H_DIM) {
        b1all[tid] = b1[tid];
        w2all[tid] = W2[tid];
    }

    // ---- prologue: stage tile tstart + orig(tstart+1) ----
    if (tid < BM) sOrig[tid] = g_perm[(size_t)tstart * BM + tid];
    if (tid < BM && tstart + 1 < tend)
        sOrig[BM + tid] = g_perm[(size_t)(tstart + 1) * BM + tid];
    __syncthreads();
    int e_cur = (sOrig[0] >= 0) ? zidx[sOrig[0]] : -1;
    if (e_cur >= 0) {
        const uint4* ghi = reinterpret_cast<const uint4*>(&g_Whi[e_cur * BWORDS]);
        const uint4* glo = reinterpret_cast<const uint4*>(&g_Wlo[e_cur * BWORDS]);
        uint4* shi = reinterpret_cast<uint4*>(BhiW);
        uint4* slo = reinterpret_cast<uint4*>(BloW);
        shi[tid] = ghi[tid]; shi[NT + tid] = ghi[NT + tid];
        slo[tid] = glo[tid]; slo[NT + tid] = glo[NT + tid];
    }
#pragma unroll
    for (int it = 0; it < 8; it++) {
        int row = it * 16 + wid;
        int o = sOrig[row];
        float4 v = make_float4(0.f, 0.f, 0.f, 0.f);
        if (o >= 0)
            v = *reinterpret_cast<const float4*>(x + (size_t)o * D_DIM + lane * 4);
        store_a(AhiW, AloW, v, row, lane);
    }
    __syncthreads();

    // fragment-lane decomposition (16 warps: 4 wm x 4 wn, warp tile 32x16)
    int wm = wid & 3;
    int wn = wid >> 2;
    int g = lane >> 2;
    int tg = lane & 3;
    int lane7 = lane & 7;
    int sub = lane >> 3;
    int subm = sub & 1;
    int subh = sub >> 1;

    uint32_t aHiBase = smem_u32(AhiW), aLoBase = smem_u32(AloW);
    uint32_t bHiBase = smem_u32(BhiW), bLoBase = smem_u32(BloW);

    int aRow0 = (wm * 32 + subm * 8 + lane7) * 64;
    int aRow1 = aRow0 + 16 * 64;
    int aXor = 4 * lane7;
    int a4h = 4 * subh;
    int bConst = (subm * 8 + lane7) * 32 + ((4 * (wn * 2 + subh)) ^ (4 * lane7));

    int p = 0;
    for (int t = tstart; t < tend; t++) {
        int pn = p ^ 1;
        bool hasNext = (t + 1 < tend);
        bool hasNext2 = (t + 2 < tend);

        // 1. prefetch A(t+1) rows into registers (latency hides under MMA)
        float4 pref[8];
        if (hasNext) {
#pragma unroll
            for (int it = 0; it < 8; it++) {
                int row = it * 16 + wid;
                int o = sOrig[pn * BM + row];
                pref[it] = make_float4(0.f, 0.f, 0.f, 0.f);
                if (o >= 0)
                    pref[it] = *reinterpret_cast<const float4*>(
                        x + (size_t)o * D_DIM + lane * 4);
            }
        }
        // 2. prefetch orig(t+2) and e(t+1)
        int o2 = -1;
        if (tid < BM && hasNext2) o2 = g_perm[(size_t)(t + 2) * BM + tid];
        int e_next = e_cur;
        if (hasNext) {
            int o0 = sOrig[pn * BM];
            e_next = (o0 >= 0) ? zidx[o0] : -1;
        }

        // 3. MMA(t)
        int eidx = (e_cur >= 0) ? e_cur : 0;
        const float* b1s = b1all + eidx * H_DIM;
        const float* w2s = w2all + eidx * H_DIM;
        float b2e = b2[eidx];

        float acc[2][2][4];
#pragma unroll
        for (int t2 = 0; t2 < 2; t2++)
#pragma unroll
            for (int u = 0; u < 2; u++)
#pragma unroll
                for (int qq = 0; qq < 4; qq++) acc[t2][u][qq] = 0.0f;

#pragma unroll
        for (int kb = 0; kb < 8; kb++) {
            int aOff = (8 * kb + a4h) ^ aXor;
            uint32_t ahi0[4], ahi1[4], alo0[4], alo1[4], bhi[4], blo[4];
            ldsm_x4(ahi0, aHiBase + (aRow0 + aOff) * 4);
            ldsm_x4(ahi1, aHiBase + (aRow1 + aOff) * 4);
            ldsm_x4(alo0, aLoBase + (aRow0 + aOff) * 4);
            ldsm_x4(alo1, aLoBase + (aRow1 + aOff) * 4);
            ldsm_x4t(bhi, bHiBase + (kb * 512 + bConst) * 4);
            ldsm_x4t(blo, bLoBase + (kb * 512 + bConst) * 4);
#pragma unroll
            for (int u = 0; u < 2; u++) {
                mma_bf16(acc[0][u], ahi0, bhi[2 * u], bhi[2 * u + 1]);
                mma_bf16(acc[0][u], ahi0, blo[2 * u], blo[2 * u + 1]);
                mma_bf16(acc[0][u], alo0, bhi[2 * u], bhi[2 * u + 1]);
                mma_bf16(acc[1][u], ahi1, bhi[2 * u], bhi[2 * u + 1]);
                mma_bf16(acc[1][u], ahi1, blo[2 * u], blo[2 * u + 1]);
                mma_bf16(acc[1][u], alo1, bhi[2 * u], bhi[2 * u + 1]);
            }
        }

        // 4. epilogue(t)
#pragma unroll
        for (int t2 = 0; t2 < 2; t2++) {
            float p0 = 0.0f, p1 = 0.0f;
#pragma unroll
            for (int u = 0; u < 2; u++) {
                int c0 = wn * 16 + u * 8 + 2 * tg;
                p0 = fmaf(sspf(acc[t2][u][0] + b1s[c0]),     w2s[c0],     p0);
                p0 = fmaf(sspf(acc[t2][u][1] + b1s[c0 + 1]), w2s[c0 + 1], p0);
                p1 = fmaf(sspf(acc[t2][u][2] + b1s[c0]),     w2s[c0],     p1);
                p1 = fmaf(sspf(acc[t2][u][3] + b1s[c0 + 1]), w2s[c0 + 1], p1);
            }
            p0 += __shfl_xor_sync(0xffffffffu, p0, 1);
            p0 += __shfl_xor_sync(0xffffffffu, p0, 2);
            p1 += __shfl_xor_sync(0xffffffffu, p1, 1);
            p1 += __shfl_xor_sync(0xffffffffu, p1, 2);
            if (tg == 0) {
                int r0 = wm * 32 + t2 * 16 + g;
                int o0 = sOrig[p * BM + r0];
                int o1 = sOrig[p * BM + r0 + 8];
                float bias = (wn == 0) ? b2e : 0.0f;
                if (o0 >= 0) atomicAdd(&out[idx_m[o0]], p0 + bias);
                if (o1 >= 0) atomicAdd(&out[idx_m[o1]], p1 + bias);
            }
        }

        __syncthreads();   // all reads of A/B/sOrig[p] complete

        // 5. stage tile t+1
        if (hasNext) {
#pragma unroll
            for (int it = 0; it < 8; it++) {
                int row = it * 16 + wid;
                store_a(AhiW, AloW, pref[it], row, lane);
            }
            if (tid < BM && hasNext2) sOrig[p * BM + tid] = o2;
            if (e_next != e_cur && e_next >= 0) {
                const uint4* ghi =
                    reinterpret_cast<const uint4*>(&g_Whi[e_next * BWORDS]);
                const uint4* glo =
                    reinterpret_cast<const uint4*>(&g_Wlo[e_next * BWORDS]);
                uint4* shi = reinterpret_cast<uint4*>(BhiW);
                uint4* slo = reinterpret_cast<uint4*>(BloW);
                shi[tid] = ghi[tid]; shi[NT + tid] = ghi[NT + tid];
                slo[tid] = glo[tid]; slo[NT + tid] = glo[NT + tid];
            }
            __syncthreads();
        }
        p = pn;
        e_cur = e_next;
    }
}

// ---------------------------------------------------------------------------
extern "C" void kernel_launch(void* const* d_in, const int* in_sizes, int n_in,
                              void* d_out, int out_size) {
    const float* x    = (const float*)d_in[0];
    const int*   zidx = (const int*)d_in[1];
    const int*   idxm = (const int*)d_in[2];
    const float* W1   = (const float*)d_in[3];
    const float* b1   = (const float*)d_in[4];
    const float* W2   = (const float*)d_in[5];
    const float* b2   = (const float*)d_in[6];
    float* out = (float*)d_out;

    int N = in_sizes[1];
    int E = in_sizes[6];
    int M = out_size;

    int ntiles = (N + BM - 1) / BM + E;
    int total_slots = ntiles * BM;
    if (total_slots > PERM_CAP) total_slots = PERM_CAP;

    static int smem_set = 0;
    if (!smem_set) {
        cudaFuncSetAttribute(k_main, cudaFuncAttributeMaxDynamicSharedMemorySize,
                             SMEM_TOTAL);
        smem_set = 1;
    }

    // 4 launches -> k_main is overall launch #6 (ncu -s 5 -c 1 target).
    k_prep<<<256, 256>>>(out, W1, E, M, total_slots);
    k_histscan<<<HIST_BLOCKS, 256>>>(zidx, N, E);
    k_scatter<<<(N + 255) / 256, 256>>>(zidx, N);
    k_main<<<GRID_PERSIST, NT, SMEM_TOTAL>>>(x, zidx, idxm, W1, b1, W2, b2,
                                             out, ntiles);
}

// round 9
// speedup vs baseline: 1.5895x; 1.0024x over previous
#include <cuda_runtime.h>
#include <cuda_bf16.h>
#include <cstdint>

// Problem constants (this instance): N=1e6 atoms, D=128, H=64, E=4, M=20000.
#define D_DIM 128
#define H_DIM 64
#define BM 128
#define NT 512
#define E_MAX 8
#define PERM_CAP 1250000
#define HIST_BLOCKS 512
#define GRID_PERSIST 148

// dynamic SMEM layout (bytes):
// A double buffered: buf s at s*65536 (AHI 32KB + ALO 32KB)
#define ABUF_STRIDE 65536
#define ALO_OFF 32768
#define OFF_BHI 131072
#define OFF_BLO 147456
#define OFF_SORIG 163840      // ring of 4 x 128 ints
#define OFF_B1ALL 165888
#define OFF_W2ALL 167936
#define OFF_ETAG  169984      // ring of 4 ints
#define SMEM_TOTAL 170496

#define BWORDS 4096           // per-element W1 image: 4096 u32 (16KB)

__device__ int g_count[E_MAX];
__device__ int g_cursor[E_MAX];
__device__ int g_done;
__device__ int g_perm[PERM_CAP];
__device__ uint32_t g_Whi[E_MAX * BWORDS];
__device__ uint32_t g_Wlo[E_MAX * BWORDS];

// ---------------------------------------------------------------------------
__global__ void k_prep(float* __restrict__ out, const float* __restrict__ W1,
                       int E, int M, int total_slots) {
    int i = blockIdx.x * blockDim.x + threadIdx.x;
    int stride = gridDim.x * blockDim.x;
    for (int j = i; j < M; j += stride) out[j] = 0.0f;
    for (int j = i; j < total_slots; j += stride) g_perm[j] = -1;
    if (i < E_MAX) g_count[i] = 0;
    if (i == E_MAX) g_done = 0;

    for (int it = i; it < E * D_DIM * 16; it += stride) {
        int e = it >> 11;
        int k = (it >> 4) & 127;
        int n4 = it & 15;
        float4 v = *reinterpret_cast<const float4*>(
            W1 + (size_t)e * D_DIM * H_DIM + (size_t)k * H_DIM + n4 * 4);
        __nv_bfloat16 hx = __float2bfloat16(v.x), hy = __float2bfloat16(v.y);
        __nv_bfloat16 hz = __float2bfloat16(v.z), hw = __float2bfloat16(v.w);
        float rx = v.x - __bfloat162float(hx), ry = v.y - __bfloat162float(hy);
        float rz = v.z - __bfloat162float(hz), rw = v.w - __bfloat162float(hw);
        __nv_bfloat162 hi01 = __halves2bfloat162(hx, hy);
        __nv_bfloat162 hi23 = __halves2bfloat162(hz, hw);
        __nv_bfloat162 lo01 = __floats2bfloat162_rn(rx, ry);
        __nv_bfloat162 lo23 = __floats2bfloat162_rn(rz, rw);
        int w = e * BWORDS + k * 32 + (((n4 >> 1) ^ (k & 7)) << 2) + (n4 & 1) * 2;
        g_Whi[w]     = *reinterpret_cast<uint32_t*>(&hi01);
        g_Whi[w + 1] = *reinterpret_cast<uint32_t*>(&hi23);
        g_Wlo[w]     = *reinterpret_cast<uint32_t*>(&lo01);
        g_Wlo[w + 1] = *reinterpret_cast<uint32_t*>(&lo23);
    }
}

__global__ void k_histscan(const int* __restrict__ zidx, int n, int E) {
    __shared__ int sh[E_MAX];
    if (threadIdx.x < E_MAX) sh[threadIdx.x] = 0;
    __syncthreads();
    int i = blockIdx.x * blockDim.x + threadIdx.x;
    int stride = gridDim.x * blockDim.x;
    for (int j = i; j < n; j += stride) atomicAdd(&sh[zidx[j]], 1);
    __syncthreads();
    if (threadIdx.x < E) atomicAdd(&g_count[threadIdx.x], sh[threadIdx.x]);
    __threadfence();
    __syncthreads();
    if (threadIdx.x == 0) {
        int t = atomicAdd(&g_done, 1);
        if (t == gridDim.x - 1) {
            int off = 0;
            for (int e = 0; e < E; e++) {
                g_cursor[e] = off;
                off += ((g_count[e] + BM - 1) / BM) * BM;
            }
        }
    }
}

__global__ void k_scatter(const int* __restrict__ zidx, int n) {
    __shared__ int s_cnt[E_MAX];
    __shared__ int s_off[E_MAX];
    if (threadIdx.x < E_MAX) s_cnt[threadIdx.x] = 0;
    __syncthreads();
    int i = blockIdx.x * blockDim.x + threadIdx.x;
    int e = -1;
    if (i < n) { e = zidx[i]; atomicAdd(&s_cnt[e], 1); }
    __syncthreads();
    if (threadIdx.x < E_MAX && s_cnt[threadIdx.x] > 0)
        s_off[threadIdx.x] = atomicAdd(&g_cursor[threadIdx.x], s_cnt[threadIdx.x]);
    __syncthreads();
    if (threadIdx.x < E_MAX) s_cnt[threadIdx.x] = 0;
    __syncthreads();
    if (i < n) {
        int pos = s_off[e] + atomicAdd(&s_cnt[e], 1);
        g_perm[pos] = i;
    }
}

__device__ __forceinline__ float sspf(float v) {
    return __logf(fmaf(0.5f, __expf(v), 0.5f));
}
__device__ __forceinline__ void mma_bf16(float* c, const uint32_t* a,
                                         const uint32_t b0, const uint32_t b1) {
    asm volatile(
        "mma.sync.aligned.m16n8k16.row.col.f32.bf16.bf16.f32 "
        "{%0,%1,%2,%3}, {%4,%5,%6,%7}, {%8,%9}, {%0,%1,%2,%3};"
        : "+f"(c[0]), "+f"(c[1]), "+f"(c[2]), "+f"(c[3])
        : "r"(a[0]), "r"(a[1]), "r"(a[2]), "r"(a[3]), "r"(b0), "r"(b1));
}
__device__ __forceinline__ void ldsm_x4(uint32_t* r, uint32_t addr) {
    asm volatile("ldmatrix.sync.aligned.m8n8.x4.shared.b16 {%0,%1,%2,%3}, [%4];"
                 : "=r"(r[0]), "=r"(r[1]), "=r"(r[2]), "=r"(r[3]) : "r"(addr));
}
__device__ __forceinline__ void ldsm_x4t(uint32_t* r, uint32_t addr) {
    asm volatile("ldmatrix.sync.aligned.m8n8.x4.trans.shared.b16 {%0,%1,%2,%3}, [%4];"
                 : "=r"(r[0]), "=r"(r[1]), "=r"(r[2]), "=r"(r[3]) : "r"(addr));
}
__device__ __forceinline__ uint32_t smem_u32(const void* p) {
    return (uint32_t)__cvta_generic_to_shared(p);
}
__device__ __forceinline__ uint32_t cvt_bf16x2(float v1, float v0) {
    uint32_t r;
    asm("cvt.rn.bf16x2.f32 %0, %1, %2;" : "=r"(r) : "f"(v1), "f"(v0));
    return r;
}

__device__ __forceinline__ void store_a(char* abase, float4 v, int row, int lane) {
    uint32_t* AhiW = reinterpret_cast<uint32_t*>(abase);
    uint32_t* AloW = reinterpret_cast<uint32_t*>(abase + ALO_OFF);
    uint32_t xi0 = __float_as_uint(v.x), xi1 = __float_as_uint(v.y);
    uint32_t xi2 = __float_as_uint(v.z), xi3 = __float_as_uint(v.w);
    uint32_t h01 = __byte_perm(xi0, xi1, 0x7632);
    uint32_t h23 = __byte_perm(xi2, xi3, 0x7632);
    float l0 = v.x - __uint_as_float(xi0 & 0xffff0000u);
    float l1 = v.y - __uint_as_float(xi1 & 0xffff0000u);
    float l2 = v.z - __uint_as_float(xi2 & 0xffff0000u);
    float l3 = v.w - __uint_as_float(xi3 & 0xffff0000u);
    uint32_t l01 = cvt_bf16x2(l1, l0);
    uint32_t l23 = cvt_bf16x2(l3, l2);
    int w = row * 64 + ((((lane >> 1) ^ (row & 7)) << 2) + (lane & 1) * 2);
    *reinterpret_cast<uint2*>(&AhiW[w]) = make_uint2(h01, h23);
    *reinterpret_cast<uint2*>(&AloW[w]) = make_uint2(l01, l23);
}

__device__ __forceinline__ void stage_B(char* smem, int e, int tid) {
    const uint4* ghi = reinterpret_cast<const uint4*>(&g_Whi[e * BWORDS]);
    const uint4* glo = reinterpret_cast<const uint4*>(&g_Wlo[e * BWORDS]);
    uint4* shi = reinterpret_cast<uint4*>(smem + OFF_BHI);
    uint4* slo = reinterpret_cast<uint4*>(smem + OFF_BLO);
    shi[tid] = ghi[tid]; shi[NT + tid] = ghi[NT + tid];
    slo[tid] = glo[tid]; slo[NT + tid] = glo[NT + tid];
}

// ---------------------------------------------------------------------------
// persistent main kernel: double-buffered A, single barrier per tile,
// depth-2 register prefetch, B re-staged only on element change.
// ---------------------------------------------------------------------------
__global__ __launch_bounds__(NT, 1)
void k_main(const float* __restrict__ x, const int* __restrict__ zidx,
            const int* __restrict__ idx_m,
            const float* __restrict__ W1, const float* __restrict__ b1,
            const float* __restrict__ W2, const float* __restrict__ b2,
            float* __restrict__ out, int ntiles) {
    extern __shared__ char smem[];
    int*   sOrig = reinterpret_cast<int*>(smem + OFF_SORIG);   // ring [4][128]
    float* b1all = reinterpret_cast<float*>(smem + OFF_B1ALL);
    float* w2all = reinterpret_cast<float*>(smem + OFF_W2ALL);
    int*   eTag  = reinterpret_cast<int*>(smem + OFF_ETAG);    // ring [4]

    int tid = threadIdx.x;
    int wid = tid >> 5;
    int lane = tid & 31;

    int q = (ntiles + gridDim.x - 1) / gridDim.x;
    int tstart = blockIdx.x * q;
    int tend = min(ntiles, tstart + q);
    if (tstart >= tend) return;
    int L = tend - tstart;

    if (tid < E_MAX * H_DIM) {
        b1all[tid] = b1[tid];
        w2all[tid] = W2[tid];
    }
    // sOrig ring slots 0..2, e-tags 0..2
    if (tid < BM) {
#pragma unroll
        for (int j = 0; j < 3; j++)
            sOrig[j * BM + tid] =
                (j < L) ? g_perm[(size_t)(tstart + j) * BM + tid] : -1;
    }
    if (tid < 3) {
        int o0 = (tid < L) ? g_perm[(size_t)(tstart + tid) * BM] : -1;
        eTag[tid] = (o0 >= 0) ? zidx[o0] : -1;
    }
    __syncthreads();

    int e_cur = eTag[0];
    if (e_cur < 0) return;     // impossible in practice (row 0 always valid)
    stage_B(smem, e_cur, tid);

    // stage A(0) into buf0
#pragma unroll
    for (int it = 0; it < 8; it++) {
        int row = it * 16 + wid;
        int o = sOrig[row];
        float4 v = make_float4(0.f, 0.f, 0.f, 0.f);
        if (o >= 0)
            v = *reinterpret_cast<const float4*>(x + (size_t)o * D_DIM + lane * 4);
        store_a(smem, v, row, lane);
    }
    // prefetch x(1)
    float4 pref[8];
    if (L > 1) {
#pragma unroll
        for (int it = 0; it < 8; it++) {
            int row = it * 16 + wid;
            int o = sOrig[BM + row];
            pref[it] = make_float4(0.f, 0.f, 0.f, 0.f);
            if (o >= 0)
                pref[it] = *reinterpret_cast<const float4*>(
                    x + (size_t)o * D_DIM + lane * 4);
        }
    }
    __syncthreads();

    // fragment-lane decomposition (16 warps: 4 wm x 4 wn, warp tile 32x16)
    int wm = wid & 3;
    int wn = wid >> 2;
    int g = lane >> 2;
    int tg = lane & 3;
    int lane7 = lane & 7;
    int sub = lane >> 3;
    int subm = sub & 1;
    int subh = sub >> 1;

    uint32_t aBase0 = smem_u32(smem);
    uint32_t bHiBase = smem_u32(smem + OFF_BHI);
    uint32_t bLoBase = smem_u32(smem + OFF_BLO);

    int aRow0 = (wm * 32 + subm * 8 + lane7) * 64;
    int aRow1 = aRow0 + 16 * 64;
    int aXor = 4 * lane7;
    int a4h = 4 * subh;
    int bConst = (subm * 8 + lane7) * 32 + ((4 * (wn * 2 + subh)) ^ (4 * lane7));

    for (int l = 0; l < L; l++) {
        int s = l & 1;
        char* abase_cur = smem + s * ABUF_STRIDE;
        char* abase_nxt = smem + (s ^ 1) * ABUF_STRIDE;

        // 1. store A(l+1) from regs prefetched last iteration
        if (l + 1 < L) {
#pragma unroll
            for (int it = 0; it < 8; it++)
                store_a(abase_nxt, pref[it], it * 16 + wid, lane);
        }
        // 2. issue LDG for perm(l+3)
        int o3 = -1;
        if (tid < BM && l + 3 < L)
            o3 = g_perm[(size_t)(tstart + l + 3) * BM + tid];
        // 3. prefetch x(l+2) (latency hides under MMA)
        if (l + 2 < L) {
            const int* so = sOrig + ((l + 2) & 3) * BM;
#pragma unroll
            for (int it = 0; it < 8; it++) {
                int row = it * 16 + wid;
                int o = so[row];
                pref[it] = make_float4(0.f, 0.f, 0.f, 0.f);
                if (o >= 0)
                    pref[it] = *reinterpret_cast<const float4*>(
                        x + (size_t)o * D_DIM + lane * 4);
            }
        }

        // 4. MMA(l) on current buffer
        uint32_t aHiBase = aBase0 + s * ABUF_STRIDE;
        uint32_t aLoBase = aHiBase + ALO_OFF;
        float acc[2][2][4];
#pragma unroll
        for (int t2 = 0; t2 < 2; t2++)
#pragma unroll
            for (int u = 0; u < 2; u++)
#pragma unroll
                for (int qq = 0; qq < 4; qq++) acc[t2][u][qq] = 0.0f;

#pragma unroll
        for (int kb = 0; kb < 8; kb++) {
            int aOff = (8 * kb + a4h) ^ aXor;
            uint32_t ahi0[4], ahi1[4], alo0[4], alo1[4], bhi[4], blo[4];
            ldsm_x4(ahi0, aHiBase + (aRow0 + aOff) * 4);
            ldsm_x4(ahi1, aHiBase + (aRow1 + aOff) * 4);
            ldsm_x4(alo0, aLoBase + (aRow0 + aOff) * 4);
            ldsm_x4(alo1, aLoBase + (aRow1 + aOff) * 4);
            ldsm_x4t(bhi, bHiBase + (kb * 512 + bConst) * 4);
            ldsm_x4t(blo, bLoBase + (kb * 512 + bConst) * 4);
#pragma unroll
            for (int u = 0; u < 2; u++) {
                mma_bf16(acc[0][u], ahi0, bhi[2 * u], bhi[2 * u + 1]);
                mma_bf16(acc[0][u], ahi0, blo[2 * u], blo[2 * u + 1]);
                mma_bf16(acc[0][u], alo0, bhi[2 * u], bhi[2 * u + 1]);
                mma_bf16(acc[1][u], ahi1, bhi[2 * u], bhi[2 * u + 1]);
                mma_bf16(acc[1][u], ahi1, blo[2 * u], blo[2 * u + 1]);
                mma_bf16(acc[1][u], alo1, bhi[2 * u], bhi[2 * u + 1]);
            }
        }

        // 5. epilogue(l)
        {
            const int* so_t = sOrig + (l & 3) * BM;
            const float* b1s = b1all + e_cur * H_DIM;
            const float* w2s = w2all + e_cur * H_DIM;
            float b2e = b2[e_cur];
#pragma unroll
            for (int t2 = 0; t2 < 2; t2++) {
                float p0 = 0.0f, p1 = 0.0f;
#pragma unroll
                for (int u = 0; u < 2; u++) {
                    int c0 = wn * 16 + u * 8 + 2 * tg;
                    p0 = fmaf(sspf(acc[t2][u][0] + b1s[c0]),     w2s[c0],     p0);
                    p0 = fmaf(sspf(acc[t2][u][1] + b1s[c0 + 1]), w2s[c0 + 1], p0);
                    p1 = fmaf(sspf(acc[t2][u][2] + b1s[c0]),     w2s[c0],     p1);
                    p1 = fmaf(sspf(acc[t2][u][3] + b1s[c0 + 1]), w2s[c0 + 1], p1);
                }
                p0 += __shfl_xor_sync(0xffffffffu, p0, 1);
                p0 += __shfl_xor_sync(0xffffffffu, p0, 2);
                p1 += __shfl_xor_sync(0xffffffffu, p1, 1);
                p1 += __shfl_xor_sync(0xffffffffu, p1, 2);
                if (tg == 0) {
                    int r0 = wm * 32 + t2 * 16 + g;
                    int o0 = so_t[r0];
                    int o1 = so_t[r0 + 8];
                    float bias = (wn == 0) ? b2e : 0.0f;
                    if (o0 >= 0) atomicAdd(&out[idx_m[o0]], p0 + bias);
                    if (o1 >= 0) atomicAdd(&out[idx_m[o1]], p1 + bias);
                }
            }
        }

        // 6. commit perm(l+3) + element tag
        if (tid < BM) sOrig[((l + 3) & 3) * BM + tid] = o3;
        if (tid == 0) eTag[(l + 3) & 3] = (o3 >= 0) ? zidx[o3] : -1;

        // 7. single barrier
        __syncthreads();

        // 8. element change (rare): reload B with extra barrier
        if (l + 1 < L) {
            int e_next = eTag[(l + 1) & 3];
            if (e_next != e_cur && e_next >= 0) {
                stage_B(smem, e_next, tid);
                __syncthreads();
            }
            if (e_next >= 0) e_cur = e_next;
        }
    }
}

// ---------------------------------------------------------------------------
extern "C" void kernel_launch(void* const* d_in, const int* in_sizes, int n_in,
                              void* d_out, int out_size) {
    const float* x    = (const float*)d_in[0];
    const int*   zidx = (const int*)d_in[1];
    const int*   idxm = (const int*)d_in[2];
    const float* W1   = (const float*)d_in[3];
    const float* b1   = (const float*)d_in[4];
    const float* W2   = (const float*)d_in[5];
    const float* b2   = (const float*)d_in[6];
    float* out = (float*)d_out;

    int N = in_sizes[1];
    int E = in_sizes[6];
    int M = out_size;

    int ntiles = (N + BM - 1) / BM + E;
    int total_slots = ntiles * BM;
    if (total_slots > PERM_CAP) total_slots = PERM_CAP;

    static int smem_set = 0;
    if (!smem_set) {
        cudaFuncSetAttribute(k_main, cudaFuncAttributeMaxDynamicSharedMemorySize,
                             SMEM_TOTAL);
        smem_set = 1;
    }

    k_prep<<<256, 256>>>(out, W1, E, M, total_slots);
    k_histscan<<<HIST_BLOCKS, 256>>>(zidx, N, E);
    k_scatter<<<(N + 255) / 256, 256>>>(zidx, N);
    k_main<<<GRID_PERSIST, NT, SMEM_TOTAL>>>(x, zidx, idxm, W1, b1, W2, b2,
                                             out, ntiles);
}